// round 5
// baseline (speedup 1.0000x reference)
#include <cuda_runtime.h>

typedef unsigned long long u64;

__device__ __forceinline__ u64 pack2(float lo, float hi) {
    u64 r; asm("mov.b64 %0, {%1, %2};" : "=l"(r) : "f"(lo), "f"(hi)); return r;
}
__device__ __forceinline__ void unpack2(u64 v, float& lo, float& hi) {
    asm("mov.b64 {%0, %1}, %2;" : "=f"(lo), "=f"(hi) : "l"(v));
}
__device__ __forceinline__ u64 ffma2(u64 a, u64 b, u64 c) {
    u64 d; asm("fma.rn.f32x2 %0, %1, %2, %3;" : "=l"(d) : "l"(a), "l"(b), "l"(c)); return d;
}
__device__ __forceinline__ void red4(float* addr, float a, float b, float c, float d) {
    asm volatile("red.global.add.v4.f32 [%0], {%1, %2, %3, %4};"
                 :: "l"(addr), "f"(a), "f"(b), "f"(c), "f"(d) : "memory");
}

#define BB 16
#define NPIX 1024
#define DD 128
#define KK 32
#define CHUNKS 64
#define ROWS_CTA 16          // NPIX / CHUNKS
#define NTHREADS 128
#define NWARPS 4
#define CWS 132              // codeword smem row stride (conflict-free float4)

__global__ void zero_kernel(float4* out, int n4) {
    int i = blockIdx.x * blockDim.x + threadIdx.x;
    if (i < n4) out[i] = make_float4(0.f, 0.f, 0.f, 0.f);
}

__global__ void __launch_bounds__(NTHREADS, 8) enc_kernel(
    const float* __restrict__ x, const float* __restrict__ cw,
    const float* __restrict__ scale, float* __restrict__ out)
{
    __shared__ __align__(16) float cw_s[KK * CWS];
    __shared__ __align__(16) float x_s[ROWS_CTA * DD];
    __shared__ float A_s[ROWS_CTA * KK];
    __shared__ float S_s[NWARPS * KK];

    const int t = threadIdx.x;
    const int lane = t & 31;
    const int w = t >> 5;
    const int b = blockIdx.y;
    const int chunk = blockIdx.x;

    // ---- stage: codewords (plain, padded stride) + x tile; x2 from load regs ----
    {
        const float4* cg = (const float4*)cw;
        #pragma unroll
        for (int i = t; i < KK * DD / 4; i += NTHREADS) {
            int k = i >> 5, d4 = i & 31;
            *(float4*)&cw_s[k * CWS + d4 * 4] = cg[i];
        }
    }
    // x tile: 512 float4, 4 passes; pass p -> thread t loads row p*4+w, cols 4*lane..
    float x2[4];
    {
        const float4* xg = (const float4*)(x + ((size_t)b * NPIX + chunk * ROWS_CTA) * DD);
        float4* xs4 = (float4*)x_s;
        #pragma unroll
        for (int p = 0; p < 4; p++) {
            float4 v = xg[p * NTHREADS + t];
            xs4[p * NTHREADS + t] = v;
            float q = v.x * v.x;
            q = fmaf(v.y, v.y, q);
            q = fmaf(v.z, v.z, q);
            x2[p] = fmaf(v.w, v.w, q);
        }
        // 4 interleaved warp reductions (rows p*4+w belong to this warp)
        #pragma unroll
        for (int off = 16; off > 0; off >>= 1) {
            #pragma unroll
            for (int p = 0; p < 4; p++) x2[p] += __shfl_xor_sync(0xffffffffu, x2[p], off);
        }
    }
    const float sc = scale[lane];
    __syncthreads();

    // ---- dot phase: warp w handles rows {w, w+4, w+8, w+12}; lane = codeword k
    // xc_j = <x_row_j, c_k>, fused c2 = <c_k, c_k>
    u64 da[8];
    u64 c2a = 0ull, c2b = 0ull;
    #pragma unroll
    for (int j = 0; j < 8; j++) da[j] = 0ull;
    const ulonglong2* cp = (const ulonglong2*)&cw_s[lane * CWS];
    #pragma unroll
    for (int i = 0; i < DD / 4; i++) {
        ulonglong2 cv = cp[i];
        c2a = ffma2(cv.x, cv.x, c2a);
        c2b = ffma2(cv.y, cv.y, c2b);
        #pragma unroll
        for (int j = 0; j < 4; j++) {
            ulonglong2 xv = ((const ulonglong2*)&x_s[(4 * j + w) * DD])[i];
            da[2 * j]     = ffma2(xv.x, cv.x, da[2 * j]);
            da[2 * j + 1] = ffma2(xv.y, cv.y, da[2 * j + 1]);
        }
    }
    float c2r;
    {
        float l0, h0, l1, h1;
        unpack2(c2a, l0, h0); unpack2(c2b, l1, h1);
        c2r = (l0 + h0) + (l1 + h1);
    }

    // ---- softmax over K=32 lanes (no max-subtraction: scale<0, logits bounded;
    //      validated at rel_err ~2.5e-7 for three rounds) ----
    float e[4], s[4];
    #pragma unroll
    for (int j = 0; j < 4; j++) {
        float l0, h0, l1, h1;
        unpack2(da[2 * j], l0, h0);
        unpack2(da[2 * j + 1], l1, h1);
        float xc = (l0 + h0) + (l1 + h1);
        float sl = sc * fmaf(-2.f, xc, x2[j] + c2r);
        e[j] = __expf(sl);
        s[j] = e[j];
    }
    #pragma unroll
    for (int off = 16; off > 0; off >>= 1) {
        #pragma unroll
        for (int j = 0; j < 4; j++) s[j] += __shfl_xor_sync(0xffffffffu, s[j], off);
    }
    float sA = 0.f;
    #pragma unroll
    for (int j = 0; j < 4; j++) {
        float a = e[j] * (1.f / s[j]);
        A_s[(4 * j + w) * KK + lane] = a;
        sA += a;
    }
    S_s[w * KK + lane] = sA;
    __syncthreads();

    // ---- E accumulate: k = lane, d slab = [w*32, w*32+32) ----
    u64 acc[16];
    #pragma unroll
    for (int j = 0; j < 16; j++) acc[j] = 0ull;
    #pragma unroll
    for (int r = 0; r < ROWS_CTA; r++) {
        float av = A_s[r * KK + lane];
        u64 pa = pack2(av, av);
        const ulonglong2* xrp = (const ulonglong2*)&x_s[r * DD + w * 32];
        #pragma unroll
        for (int j = 0; j < 8; j++) {
            ulonglong2 xv = xrp[j];
            acc[2 * j]     = ffma2(pa, xv.x, acc[2 * j]);
            acc[2 * j + 1] = ffma2(pa, xv.y, acc[2 * j + 1]);
        }
    }

    // total assignment mass for this CTA's rows: S[k]
    float Sk = 0.f;
    #pragma unroll
    for (int r = 0; r < NWARPS; r++) Sk += S_s[r * KK + lane];
    const float nSk = -Sk;

    // ---- epilogue: E += acc - Sk*c, vector reduction straight to out ----
    float* ob = out + ((size_t)(b * KK + lane)) * DD + w * 32;
    const float* cr = &cw_s[lane * CWS + w * 32];
    #pragma unroll
    for (int j = 0; j < 8; j++) {
        float a0, a1, a2, a3;
        unpack2(acc[2 * j], a0, a1);
        unpack2(acc[2 * j + 1], a2, a3);
        red4(&ob[4 * j],
             fmaf(nSk, cr[4 * j + 0], a0),
             fmaf(nSk, cr[4 * j + 1], a1),
             fmaf(nSk, cr[4 * j + 2], a2),
             fmaf(nSk, cr[4 * j + 3], a3));
    }
}

extern "C" void kernel_launch(void* const* d_in, const int* in_sizes, int n_in,
                              void* d_out, int out_size) {
    const float* x  = (const float*)d_in[0];
    const float* cw = (const float*)d_in[1];
    const float* sc = (const float*)d_in[2];
    float* out = (float*)d_out;

    int n4 = out_size / 4;                 // 16384 float4
    zero_kernel<<<(n4 + 255) / 256, 256>>>((float4*)out, n4);

    dim3 grid(CHUNKS, BB);
    enc_kernel<<<grid, NTHREADS>>>(x, cw, sc, out);
}

// round 6
// speedup vs baseline: 1.0889x; 1.0889x over previous
#include <cuda_runtime.h>

typedef unsigned long long u64;

__device__ __forceinline__ u64 pack2(float lo, float hi) {
    u64 r; asm("mov.b64 %0, {%1, %2};" : "=l"(r) : "f"(lo), "f"(hi)); return r;
}
__device__ __forceinline__ void unpack2(u64 v, float& lo, float& hi) {
    asm("mov.b64 {%0, %1}, %2;" : "=f"(lo), "=f"(hi) : "l"(v));
}
__device__ __forceinline__ u64 ffma2(u64 a, u64 b, u64 c) {
    u64 d; asm("fma.rn.f32x2 %0, %1, %2, %3;" : "=l"(d) : "l"(a), "l"(b), "l"(c)); return d;
}
__device__ __forceinline__ void red4(float* addr, float a, float b, float c, float d) {
    asm volatile("red.global.add.v4.f32 [%0], {%1, %2, %3, %4};"
                 :: "l"(addr), "f"(a), "f"(b), "f"(c), "f"(d) : "memory");
}

#define BB 16
#define NPIX 1024
#define DD 128
#define KK 32
#define CHUNKS 32
#define ROWS_CTA 32
#define NTHREADS 512
#define CWS 132              // codeword smem row stride (conflict-free float4)

__global__ void zero_kernel(float4* out, int n4) {
    int i = blockIdx.x * blockDim.x + threadIdx.x;
    if (i < n4) out[i] = make_float4(0.f, 0.f, 0.f, 0.f);
}

__global__ void __launch_bounds__(NTHREADS, 3) enc_kernel(
    const float* __restrict__ x, const float* __restrict__ cw,
    const float* __restrict__ scale, float* __restrict__ out)
{
    __shared__ __align__(16) float cw_s[KK * CWS];          // 16.9 KB
    __shared__ __align__(16) float x_s[ROWS_CTA * DD];      // 16 KB
    __shared__ float P_s[2 * ROWS_CTA * KK];                // 8 KB partial dots
    __shared__ float A_s[ROWS_CTA * KK];                    // 4 KB
    __shared__ float S_s[16 * KK];                          // 2 KB
    __shared__ float x2_s[ROWS_CTA];
    __shared__ float c2_s[KK];

    const int t = threadIdx.x;
    const int lane = t & 31;
    const int w = t >> 5;          // 0..15
    const int b = blockIdx.y;
    const int chunk = blockIdx.x;

    // ---- stage: codewords + x tile; x2 and c2 from load registers ----
    {
        const float4* cg = (const float4*)cw;
        const float4* xg = (const float4*)(x + ((size_t)b * NPIX + chunk * ROWS_CTA) * DD);
        float4* xs4 = (float4*)x_s;

        float q[4];   // q[0],q[1]: x2 partials rows w, w+16; q[2],q[3]: c2 partials k=w, w+16
        #pragma unroll
        for (int p = 0; p < 2; p++) {
            // x: f4 index i = p*512 + t -> row = 16p + w, col4 = lane
            float4 v = xg[p * NTHREADS + t];
            xs4[p * NTHREADS + t] = v;
            float s = v.x * v.x;
            s = fmaf(v.y, v.y, s);
            s = fmaf(v.z, v.z, s);
            q[p] = fmaf(v.w, v.w, s);
            // cw: f4 index i = p*512 + t -> k = 16p + w, d4 = lane
            float4 c = cg[p * NTHREADS + t];
            *(float4*)&cw_s[(16 * p + w) * CWS + lane * 4] = c;
            float u = c.x * c.x;
            u = fmaf(c.y, c.y, u);
            u = fmaf(c.z, c.z, u);
            q[2 + p] = fmaf(c.w, c.w, u);
        }
        // 4 interleaved butterfly reductions
        #pragma unroll
        for (int off = 16; off > 0; off >>= 1) {
            #pragma unroll
            for (int j = 0; j < 4; j++) q[j] += __shfl_xor_sync(0xffffffffu, q[j], off);
        }
        if (lane == 0) {
            x2_s[w]      = q[0];
            x2_s[16 + w] = q[1];
            c2_s[w]      = q[2];
            c2_s[16 + w] = q[3];
        }
    }
    const float sc = scale[lane];
    __syncthreads();

    // ---- dot phase (D-split): warp = (w2 = w&7 row-group, h = w>>3 d-half)
    // rows {w2, w2+8, w2+16, w2+24}, d in [h*64, h*64+64); lane = codeword k
    {
        const int w2 = w & 7;
        const int h = w >> 3;
        u64 da[8];
        #pragma unroll
        for (int j = 0; j < 8; j++) da[j] = 0ull;
        const ulonglong2* cp = (const ulonglong2*)&cw_s[lane * CWS + h * 64];
        #pragma unroll
        for (int i = 0; i < 16; i++) {
            ulonglong2 cv = cp[i];
            #pragma unroll
            for (int j = 0; j < 4; j++) {
                ulonglong2 xv = *(const ulonglong2*)&x_s[(8 * j + w2) * DD + h * 64 + 4 * i];
                da[2 * j]     = ffma2(xv.x, cv.x, da[2 * j]);
                da[2 * j + 1] = ffma2(xv.y, cv.y, da[2 * j + 1]);
            }
        }
        #pragma unroll
        for (int j = 0; j < 4; j++) {
            float l0, h0, l1, h1;
            unpack2(da[2 * j], l0, h0);
            unpack2(da[2 * j + 1], l1, h1);
            P_s[(h * ROWS_CTA + 8 * j + w2) * KK + lane] = (l0 + h0) + (l1 + h1);
        }
    }
    __syncthreads();

    // ---- softmax: warp w handles rows {w, w+16} (no max-subtraction: scale<0,
    //      logits bounded; validated rel_err ~2.5e-7 across rounds) ----
    {
        float e[2], s[2];
        #pragma unroll
        for (int j = 0; j < 2; j++) {
            int r = w + 16 * j;
            float xc = P_s[r * KK + lane] + P_s[(ROWS_CTA + r) * KK + lane];
            float sl = sc * fmaf(-2.f, xc, x2_s[r] + c2_s[lane]);
            e[j] = __expf(sl);
            s[j] = e[j];
        }
        #pragma unroll
        for (int off = 16; off > 0; off >>= 1) {
            #pragma unroll
            for (int j = 0; j < 2; j++) s[j] += __shfl_xor_sync(0xffffffffu, s[j], off);
        }
        float sA = 0.f;
        #pragma unroll
        for (int j = 0; j < 2; j++) {
            float a = e[j] * (1.f / s[j]);
            A_s[(w + 16 * j) * KK + lane] = a;
            sA += a;
        }
        S_s[w * KK + lane] = sA;
    }
    __syncthreads();

    // ---- E accumulate: k = lane, d slab = [w*8, w*8+8) ----
    u64 acc[4];
    #pragma unroll
    for (int j = 0; j < 4; j++) acc[j] = 0ull;
    #pragma unroll
    for (int r = 0; r < ROWS_CTA; r++) {
        float av = A_s[r * KK + lane];
        u64 pa = pack2(av, av);
        const ulonglong2* xrp = (const ulonglong2*)&x_s[r * DD + w * 8];
        ulonglong2 xv0 = xrp[0];
        ulonglong2 xv1 = xrp[1];
        acc[0] = ffma2(pa, xv0.x, acc[0]);
        acc[1] = ffma2(pa, xv0.y, acc[1]);
        acc[2] = ffma2(pa, xv1.x, acc[2]);
        acc[3] = ffma2(pa, xv1.y, acc[3]);
    }

    // total assignment mass S[k] over this CTA's rows
    float Sk = 0.f;
    #pragma unroll
    for (int i = 0; i < 16; i++) Sk += S_s[i * KK + lane];
    const float nSk = -Sk;

    // ---- epilogue: E += acc - Sk*c, vector reduction straight to out ----
    float* ob = out + ((size_t)(b * KK + lane)) * DD + w * 8;
    const float* cr = &cw_s[lane * CWS + w * 8];
    #pragma unroll
    for (int j = 0; j < 2; j++) {
        float a0, a1, a2, a3;
        unpack2(acc[2 * j], a0, a1);
        unpack2(acc[2 * j + 1], a2, a3);
        red4(&ob[4 * j],
             fmaf(nSk, cr[4 * j + 0], a0),
             fmaf(nSk, cr[4 * j + 1], a1),
             fmaf(nSk, cr[4 * j + 2], a2),
             fmaf(nSk, cr[4 * j + 3], a3));
    }
}

extern "C" void kernel_launch(void* const* d_in, const int* in_sizes, int n_in,
                              void* d_out, int out_size) {
    const float* x  = (const float*)d_in[0];
    const float* cw = (const float*)d_in[1];
    const float* sc = (const float*)d_in[2];
    float* out = (float*)d_out;

    int n4 = out_size / 4;                 // 16384 float4
    zero_kernel<<<(n4 + 255) / 256, 256>>>((float4*)out, n4);

    dim3 grid(CHUNKS, BB);
    enc_kernel<<<grid, NTHREADS>>>(x, cw, sc, out);
}

// round 7
// speedup vs baseline: 1.1027x; 1.0127x over previous
#include <cuda_runtime.h>

typedef unsigned long long u64;

__device__ __forceinline__ u64 pack2(float lo, float hi) {
    u64 r; asm("mov.b64 %0, {%1, %2};" : "=l"(r) : "f"(lo), "f"(hi)); return r;
}
__device__ __forceinline__ void unpack2(u64 v, float& lo, float& hi) {
    asm("mov.b64 {%0, %1}, %2;" : "=f"(lo), "=f"(hi) : "l"(v));
}
__device__ __forceinline__ u64 ffma2(u64 a, u64 b, u64 c) {
    u64 d; asm("fma.rn.f32x2 %0, %1, %2, %3;" : "=l"(d) : "l"(a), "l"(b), "l"(c)); return d;
}
__device__ __forceinline__ void red4(float* addr, float a, float b, float c, float d) {
    asm volatile("red.global.add.v4.f32 [%0], {%1, %2, %3, %4};"
                 :: "l"(addr), "f"(a), "f"(b), "f"(c), "f"(d) : "memory");
}

#define BB 16
#define NPIX 1024
#define DD 128
#define KK 32
#define CHUNKS 32
#define ROWS_CTA 32          // NPIX / CHUNKS
#define NTHREADS 256
#define NWARPS 8
#define CWS 132              // codeword smem row stride (conflict-free float4)

__global__ void zero_kernel(float4* out, int n4) {
    int i = blockIdx.x * blockDim.x + threadIdx.x;
    if (i < n4) out[i] = make_float4(0.f, 0.f, 0.f, 0.f);
}

__global__ void __launch_bounds__(NTHREADS, 4) enc_kernel(
    const float* __restrict__ x, const float* __restrict__ cw,
    const float* __restrict__ scale, float* __restrict__ out)
{
    __shared__ __align__(16) float cw_s[KK * CWS];
    __shared__ __align__(16) float x_s[ROWS_CTA * DD];
    __shared__ float A_s[ROWS_CTA * KK];
    __shared__ float S_s[NWARPS * KK];

    const int t = threadIdx.x;
    const int lane = t & 31;
    const int w = t >> 5;
    const int b = blockIdx.y;
    const int chunk = blockIdx.x;

    // ---- stage: x first (DRAM-latency loads), then codewords (L2 hits).
    //      x2 for this warp's 4 rows comes free from the load registers.
    float x2[4];
    {
        const float4* xg = (const float4*)(x + ((size_t)b * NPIX + chunk * ROWS_CTA) * DD);
        float4* xs4 = (float4*)x_s;
        #pragma unroll
        for (int p = 0; p < 4; p++) {
            // f4 index p*256+t -> row = 8p + w, col4 = lane  (this warp's rows)
            float4 v = xg[p * NTHREADS + t];
            xs4[p * NTHREADS + t] = v;
            float q = v.x * v.x;
            q = fmaf(v.y, v.y, q);
            q = fmaf(v.z, v.z, q);
            x2[p] = fmaf(v.w, v.w, q);
        }
        const float4* cg = (const float4*)cw;
        #pragma unroll
        for (int i = t; i < KK * DD / 4; i += NTHREADS) {
            int k = i >> 5, d4 = i & 31;
            *(float4*)&cw_s[k * CWS + d4 * 4] = cg[i];
        }
        // 4 interleaved butterfly reductions for x2
        #pragma unroll
        for (int off = 16; off > 0; off >>= 1) {
            #pragma unroll
            for (int p = 0; p < 4; p++) x2[p] += __shfl_xor_sync(0xffffffffu, x2[p], off);
        }
    }
    const float sc = scale[lane];
    __syncthreads();

    // ---- dot phase: warp w rows {w, w+8, w+16, w+24}; lane = codeword k.
    //      cv (conflict-free LDS.128) software-pipelined one iteration ahead.
    u64 da[8];
    u64 c2a = 0ull, c2b = 0ull;
    #pragma unroll
    for (int j = 0; j < 8; j++) da[j] = 0ull;
    const ulonglong2* cp = (const ulonglong2*)&cw_s[lane * CWS];
    {
        ulonglong2 cv = cp[0];
        #pragma unroll
        for (int i = 0; i < DD / 4; i++) {
            ulonglong2 cvn;
            if (i + 1 < DD / 4) cvn = cp[i + 1];
            c2a = ffma2(cv.x, cv.x, c2a);
            c2b = ffma2(cv.y, cv.y, c2b);
            #pragma unroll
            for (int j = 0; j < 4; j++) {
                ulonglong2 xv = *(const ulonglong2*)&x_s[(8 * j + w) * DD + 4 * i];
                da[2 * j]     = ffma2(xv.x, cv.x, da[2 * j]);
                da[2 * j + 1] = ffma2(xv.y, cv.y, da[2 * j + 1]);
            }
            cv = cvn;
        }
    }
    float c2r;
    {
        float l0, h0, l1, h1;
        unpack2(c2a, l0, h0); unpack2(c2b, l1, h1);
        c2r = (l0 + h0) + (l1 + h1);
    }
    const float sc2 = sc * c2r;       // sc * ||c||^2
    const float scm2 = -2.f * sc;     // -2 * sc

    // ---- softmax over K=32 lanes (no max-subtraction: scale<0, logits bounded;
    //      validated at rel_err ~2.5e-7 across rounds) ----
    float e[4], s[4];
    #pragma unroll
    for (int j = 0; j < 4; j++) {
        float l0, h0, l1, h1;
        unpack2(da[2 * j], l0, h0);
        unpack2(da[2 * j + 1], l1, h1);
        float xc = (l0 + h0) + (l1 + h1);
        float sl = fmaf(sc, x2[j], fmaf(scm2, xc, sc2));
        e[j] = __expf(sl);
        s[j] = e[j];
    }
    #pragma unroll
    for (int off = 16; off > 0; off >>= 1) {
        #pragma unroll
        for (int j = 0; j < 4; j++) s[j] += __shfl_xor_sync(0xffffffffu, s[j], off);
    }
    float sA = 0.f;
    #pragma unroll
    for (int j = 0; j < 4; j++) {
        float a = e[j] * __fdividef(1.f, s[j]);
        A_s[(8 * j + w) * KK + lane] = a;
        sA += a;
    }
    S_s[w * KK + lane] = sA;
    __syncthreads();

    // Sk reduction issued BEFORE the E loop so its LDS latency overlaps compute
    float Sk = 0.f;
    #pragma unroll
    for (int r = 0; r < NWARPS; r++) Sk += S_s[r * KK + lane];

    // ---- E accumulate: k = lane, d slab = [w*16, w*16+16); pipelined ----
    u64 acc[8];
    #pragma unroll
    for (int j = 0; j < 8; j++) acc[j] = 0ull;
    {
        float av = A_s[lane];
        ulonglong2 xv0 = *(const ulonglong2*)&x_s[w * 16];
        ulonglong2 xv1 = *(const ulonglong2*)&x_s[w * 16 + 4];
        #pragma unroll
        for (int r = 0; r < ROWS_CTA; r++) {
            float avn;
            ulonglong2 nv0, nv1;
            if (r + 1 < ROWS_CTA) {
                avn = A_s[(r + 1) * KK + lane];
                nv0 = *(const ulonglong2*)&x_s[(r + 1) * DD + w * 16];
                nv1 = *(const ulonglong2*)&x_s[(r + 1) * DD + w * 16 + 4];
            }
            u64 pa = pack2(av, av);
            acc[0] = ffma2(pa, xv0.x, acc[0]);
            acc[1] = ffma2(pa, xv0.y, acc[1]);
            acc[2] = ffma2(pa, xv1.x, acc[2]);
            acc[3] = ffma2(pa, xv1.y, acc[3]);
            // second half of the 16-float slab
            ulonglong2 yv0 = *(const ulonglong2*)&x_s[r * DD + w * 16 + 8];
            ulonglong2 yv1 = *(const ulonglong2*)&x_s[r * DD + w * 16 + 12];
            acc[4] = ffma2(pa, yv0.x, acc[4]);
            acc[5] = ffma2(pa, yv0.y, acc[5]);
            acc[6] = ffma2(pa, yv1.x, acc[6]);
            acc[7] = ffma2(pa, yv1.y, acc[7]);
            av = avn; xv0 = nv0; xv1 = nv1;
        }
    }
    const float nSk = -Sk;

    float accf[16];
    #pragma unroll
    for (int j = 0; j < 8; j++) unpack2(acc[j], accf[2 * j], accf[2 * j + 1]);

    // ---- epilogue: E += acc - Sk*c, vector reduction straight to out ----
    float* ob = out + ((size_t)(b * KK + lane)) * DD + w * 16;
    const float* cr = &cw_s[lane * CWS + w * 16];
    #pragma unroll
    for (int j = 0; j < 4; j++) {
        red4(&ob[4 * j],
             fmaf(nSk, cr[4 * j + 0], accf[4 * j + 0]),
             fmaf(nSk, cr[4 * j + 1], accf[4 * j + 1]),
             fmaf(nSk, cr[4 * j + 2], accf[4 * j + 2]),
             fmaf(nSk, cr[4 * j + 3], accf[4 * j + 3]));
    }
}

extern "C" void kernel_launch(void* const* d_in, const int* in_sizes, int n_in,
                              void* d_out, int out_size) {
    const float* x  = (const float*)d_in[0];
    const float* cw = (const float*)d_in[1];
    const float* sc = (const float*)d_in[2];
    float* out = (float*)d_out;

    int n4 = out_size / 4;                 // 16384 float4
    zero_kernel<<<(n4 + 255) / 256, 256>>>((float4*)out, n4);

    dim3 grid(CHUNKS, BB);
    enc_kernel<<<grid, NTHREADS>>>(x, cw, sc, out);
}

// round 8
// speedup vs baseline: 1.1951x; 1.0838x over previous
#include <cuda_runtime.h>

typedef unsigned long long u64;

__device__ __forceinline__ u64 pack2(float lo, float hi) {
    u64 r; asm("mov.b64 %0, {%1, %2};" : "=l"(r) : "f"(lo), "f"(hi)); return r;
}
__device__ __forceinline__ void unpack2(u64 v, float& lo, float& hi) {
    asm("mov.b64 {%0, %1}, %2;" : "=f"(lo), "=f"(hi) : "l"(v));
}
__device__ __forceinline__ u64 ffma2(u64 a, u64 b, u64 c) {
    u64 d; asm("fma.rn.f32x2 %0, %1, %2, %3;" : "=l"(d) : "l"(a), "l"(b), "l"(c)); return d;
}
__device__ __forceinline__ void red4(float* addr, float a, float b, float c, float d) {
    asm volatile("red.global.add.v4.f32 [%0], {%1, %2, %3, %4};"
                 :: "l"(addr), "f"(a), "f"(b), "f"(c), "f"(d) : "memory");
}

#define BB 16
#define NPIX 1024
#define DD 128
#define KK 32
#define CHUNKS 32
#define ROWS_CTA 32          // NPIX / CHUNKS
#define NTHREADS 256
#define NWARPS 8
#define CWS 132              // codeword smem row stride (conflict-free float4)

__global__ void zero_kernel(float4* out, int n4) {
    int i = blockIdx.x * blockDim.x + threadIdx.x;
    if (i < n4) out[i] = make_float4(0.f, 0.f, 0.f, 0.f);
}

__global__ void __launch_bounds__(NTHREADS, 4) enc_kernel(
    const float* __restrict__ x, const float* __restrict__ cw,
    const float* __restrict__ scale, float* __restrict__ out)
{
    __shared__ __align__(16) float cw_s[KK * CWS];
    __shared__ __align__(16) float x_s[ROWS_CTA * DD];
    __shared__ float A_s[ROWS_CTA * KK];
    __shared__ float S_s[NWARPS * KK];

    const int t = threadIdx.x;
    const int lane = t & 31;
    const int w = t >> 5;
    const int b = blockIdx.y;
    const int chunk = blockIdx.x;

    // ---- stage: x first (DRAM-latency loads), then codewords (L2 hits).
    //      x2 for this warp's 4 rows comes free from the load registers.
    float x2[4];
    {
        const float4* xg = (const float4*)(x + ((size_t)b * NPIX + chunk * ROWS_CTA) * DD);
        float4* xs4 = (float4*)x_s;
        #pragma unroll
        for (int p = 0; p < 4; p++) {
            // f4 index p*256+t -> row = 8p + w, col4 = lane  (this warp's rows)
            float4 v = xg[p * NTHREADS + t];
            xs4[p * NTHREADS + t] = v;
            float q = v.x * v.x;
            q = fmaf(v.y, v.y, q);
            q = fmaf(v.z, v.z, q);
            x2[p] = fmaf(v.w, v.w, q);
        }
        const float4* cg = (const float4*)cw;
        #pragma unroll
        for (int i = t; i < KK * DD / 4; i += NTHREADS) {
            int k = i >> 5, d4 = i & 31;
            *(float4*)&cw_s[k * CWS + d4 * 4] = cg[i];
        }
        // 4 interleaved butterfly reductions for x2
        #pragma unroll
        for (int off = 16; off > 0; off >>= 1) {
            #pragma unroll
            for (int p = 0; p < 4; p++) x2[p] += __shfl_xor_sync(0xffffffffu, x2[p], off);
        }
    }
    const float sc = scale[lane];
    __syncthreads();

    // ---- dot phase: warp w rows {w, w+8, w+16, w+24}; lane = codeword k.
    //      cv (conflict-free LDS.128) software-pipelined one iteration ahead.
    u64 da[8];
    u64 c2a = 0ull, c2b = 0ull;
    #pragma unroll
    for (int j = 0; j < 8; j++) da[j] = 0ull;
    const ulonglong2* cp = (const ulonglong2*)&cw_s[lane * CWS];
    {
        ulonglong2 cv = cp[0];
        #pragma unroll
        for (int i = 0; i < DD / 4; i++) {
            ulonglong2 cvn;
            if (i + 1 < DD / 4) cvn = cp[i + 1];
            c2a = ffma2(cv.x, cv.x, c2a);
            c2b = ffma2(cv.y, cv.y, c2b);
            #pragma unroll
            for (int j = 0; j < 4; j++) {
                ulonglong2 xv = *(const ulonglong2*)&x_s[(8 * j + w) * DD + 4 * i];
                da[2 * j]     = ffma2(xv.x, cv.x, da[2 * j]);
                da[2 * j + 1] = ffma2(xv.y, cv.y, da[2 * j + 1]);
            }
            cv = cvn;
        }
    }
    float c2r;
    {
        float l0, h0, l1, h1;
        unpack2(c2a, l0, h0); unpack2(c2b, l1, h1);
        c2r = (l0 + h0) + (l1 + h1);
    }
    const float sc2 = sc * c2r;       // sc * ||c||^2
    const float scm2 = -2.f * sc;     // -2 * sc

    // ---- softmax over K=32 lanes (no max-subtraction: scale<0, logits bounded;
    //      validated at rel_err ~2.5e-7 across rounds) ----
    float e[4], s[4];
    #pragma unroll
    for (int j = 0; j < 4; j++) {
        float l0, h0, l1, h1;
        unpack2(da[2 * j], l0, h0);
        unpack2(da[2 * j + 1], l1, h1);
        float xc = (l0 + h0) + (l1 + h1);
        float sl = fmaf(sc, x2[j], fmaf(scm2, xc, sc2));
        e[j] = __expf(sl);
        s[j] = e[j];
    }
    #pragma unroll
    for (int off = 16; off > 0; off >>= 1) {
        #pragma unroll
        for (int j = 0; j < 4; j++) s[j] += __shfl_xor_sync(0xffffffffu, s[j], off);
    }
    float sA = 0.f;
    #pragma unroll
    for (int j = 0; j < 4; j++) {
        float a = e[j] * __fdividef(1.f, s[j]);
        A_s[(8 * j + w) * KK + lane] = a;
        sA += a;
    }
    S_s[w * KK + lane] = sA;
    __syncthreads();

    // Sk reduction issued BEFORE the E loop so its LDS latency overlaps compute
    float Sk = 0.f;
    #pragma unroll
    for (int r = 0; r < NWARPS; r++) Sk += S_s[r * KK + lane];

    // ---- E accumulate: k = lane, d slab = [w*16, w*16+16); pipelined ----
    u64 acc[8];
    #pragma unroll
    for (int j = 0; j < 8; j++) acc[j] = 0ull;
    {
        float av = A_s[lane];
        ulonglong2 xv0 = *(const ulonglong2*)&x_s[w * 16];
        ulonglong2 xv1 = *(const ulonglong2*)&x_s[w * 16 + 4];
        #pragma unroll
        for (int r = 0; r < ROWS_CTA; r++) {
            float avn;
            ulonglong2 nv0, nv1;
            if (r + 1 < ROWS_CTA) {
                avn = A_s[(r + 1) * KK + lane];
                nv0 = *(const ulonglong2*)&x_s[(r + 1) * DD + w * 16];
                nv1 = *(const ulonglong2*)&x_s[(r + 1) * DD + w * 16 + 4];
            }
            u64 pa = pack2(av, av);
            acc[0] = ffma2(pa, xv0.x, acc[0]);
            acc[1] = ffma2(pa, xv0.y, acc[1]);
            acc[2] = ffma2(pa, xv1.x, acc[2]);
            acc[3] = ffma2(pa, xv1.y, acc[3]);
            // second half of the 16-float slab
            ulonglong2 yv0 = *(const ulonglong2*)&x_s[r * DD + w * 16 + 8];
            ulonglong2 yv1 = *(const ulonglong2*)&x_s[r * DD + w * 16 + 12];
            acc[4] = ffma2(pa, yv0.x, acc[4]);
            acc[5] = ffma2(pa, yv0.y, acc[5]);
            acc[6] = ffma2(pa, yv1.x, acc[6]);
            acc[7] = ffma2(pa, yv1.y, acc[7]);
            av = avn; xv0 = nv0; xv1 = nv1;
        }
    }
    const float nSk = -Sk;

    float accf[16];
    #pragma unroll
    for (int j = 0; j < 8; j++) unpack2(acc[j], accf[2 * j], accf[2 * j + 1]);

    // ---- epilogue: E += acc - Sk*c, vector reduction straight to out ----
    float* ob = out + ((size_t)(b * KK + lane)) * DD + w * 16;
    const float* cr = &cw_s[lane * CWS + w * 16];
    #pragma unroll
    for (int j = 0; j < 4; j++) {
        red4(&ob[4 * j],
             fmaf(nSk, cr[4 * j + 0], accf[4 * j + 0]),
             fmaf(nSk, cr[4 * j + 1], accf[4 * j + 1]),
             fmaf(nSk, cr[4 * j + 2], accf[4 * j + 2]),
             fmaf(nSk, cr[4 * j + 3], accf[4 * j + 3]));
    }
}

extern "C" void kernel_launch(void* const* d_in, const int* in_sizes, int n_in,
                              void* d_out, int out_size) {
    const float* x  = (const float*)d_in[0];
    const float* cw = (const float*)d_in[1];
    const float* sc = (const float*)d_in[2];
    float* out = (float*)d_out;

    int n4 = out_size / 4;                 // 16384 float4
    zero_kernel<<<(n4 + 255) / 256, 256>>>((float4*)out, n4);

    dim3 grid(CHUNKS, BB);
    enc_kernel<<<grid, NTHREADS>>>(x, cw, sc, out);
}